// round 10
// baseline (speedup 1.0000x reference)
#include <cuda_runtime.h>

// L1Attn: attn[b,i,j,h] = -(1/sqrt(64)) * sum_w |q[b,j,h,w] - k[b,i,h,w]|
// q,k: [2, 512, 8, 64] fp32.  out: [2, 512(i=key), 512(j=query), 8] fp32.
//
// R8: 32i x 16j tile, 256 thr (warp==head), per-thread 4i x 4j f32x2 tile,
// WC=16, q register-resident / k streamed, launch_bounds(256,4).

#define NCTX 512
#define NH   8
#define WID  64
#define TI   32      // keys per block
#define TJ   16      // queries per block
#define WC   16      // w-chunk held in smem
#define RSTR 132     // row stride: 8 heads * 16 w + 4 pad (== 4 mod 32 banks)
#define OSTR 132     // output staging row stride (multiple of 4)

__device__ __forceinline__ unsigned long long addf32x2(unsigned long long a,
                                                       unsigned long long b) {
    unsigned long long r;
    asm("add.rn.f32x2 %0, %1, %2;" : "=l"(r) : "l"(a), "l"(b));
    return r;
}

__global__ void __launch_bounds__(256, 4)
l1attn_kernel(const float* __restrict__ q, const float* __restrict__ k,
              float* __restrict__ out) {
    // smem: q tile 16 rows + k tile 32 rows, RSTR floats each = 6336 floats
    // (25.3 KB). Reused as output staging (needs 31*132+128 = 4220 <= 6336).
    __shared__ __align__(16) float smem[(TJ + TI) * RSTR];
    float* qs = smem;
    float* ks = smem + TJ * RSTR;   // holds -k

    const int tid  = threadIdx.x;
    const int h    = tid >> 5;     // warp id == head
    const int lane = tid & 31;
    const int ig   = lane >> 2;    // 0..7  -> i = ig + 8*r
    const int jg   = lane & 3;     // 0..3  -> j = jg + 4*jj

    const int j0 = blockIdx.x * TJ;
    const int i0 = blockIdx.y * TI;
    const int b  = blockIdx.z;

    const unsigned long long ABSM = 0x7FFFFFFF7FFFFFFFULL;

    unsigned long long acc[4][4];
#pragma unroll
    for (int r = 0; r < 4; r++)
#pragma unroll
        for (int jj = 0; jj < 4; jj++) acc[r][jj] = 0ULL;

    for (int c = 0; c < WID / WC; c++) {
        if (c) __syncthreads();
        const int wc = c * WC;
        // q tile: 16 rows x 8 h x 16 w = 512 float4, 2 passes.
#pragma unroll
        for (int pass = 0; pass < 2; pass++) {
            int fidx = pass * 256 + tid;
            int w4   = fidx & 3;
            int hl   = (fidx >> 2) & 7;
            int row  = fidx >> 5;          // 0..15
            int goff = (((b * NCTX + j0 + row) * NH + hl) * WID) + wc + w4 * 4;
            *reinterpret_cast<float4*>(&qs[row * RSTR + hl * WC + w4 * 4]) =
                *reinterpret_cast<const float4*>(q + goff);
        }
        // k tile (negated): 32 rows x 8 h x 16 w = 1024 float4, 4 passes.
#pragma unroll
        for (int pass = 0; pass < 4; pass++) {
            int fidx = pass * 256 + tid;
            int w4   = fidx & 3;
            int hl   = (fidx >> 2) & 7;
            int row  = fidx >> 5;          // 0..31
            int koff = (((b * NCTX + i0 + row) * NH + hl) * WID) + wc + w4 * 4;
            float4 kv4 = *reinterpret_cast<const float4*>(k + koff);
            kv4.x = -kv4.x; kv4.y = -kv4.y; kv4.z = -kv4.z; kv4.w = -kv4.w;
            *reinterpret_cast<float4*>(&ks[row * RSTR + hl * WC + w4 * 4]) = kv4;
        }
        __syncthreads();

#pragma unroll
        for (int w4 = 0; w4 < WC / 4; w4++) {
            // q register-resident (4 x 16B), k streamed per i-group.
            unsigned long long qv[4][2];
#pragma unroll
            for (int jj = 0; jj < 4; jj++) {
                ulonglong2 t = *reinterpret_cast<const ulonglong2*>(
                    &qs[(jg + 4 * jj) * RSTR + h * WC + w4 * 4]);
                qv[jj][0] = t.x; qv[jj][1] = t.y;
            }
#pragma unroll
            for (int r = 0; r < 4; r++) {
                ulonglong2 kv = *reinterpret_cast<const ulonglong2*>(
                    &ks[(ig + 8 * r) * RSTR + h * WC + w4 * 4]);
#pragma unroll
                for (int jj = 0; jj < 4; jj++) {
                    unsigned long long d0 = addf32x2(qv[jj][0], kv.x) & ABSM;
                    acc[r][jj] = addf32x2(acc[r][jj], d0);
                    unsigned long long d1 = addf32x2(qv[jj][1], kv.y) & ABSM;
                    acc[r][jj] = addf32x2(acc[r][jj], d1);
                }
            }
        }
    }

    __syncthreads();
    // Stage results: stage[i][j*8+h]; each i-row = 128 contiguous out floats.
#pragma unroll
    for (int r = 0; r < 4; r++)
#pragma unroll
        for (int jj = 0; jj < 4; jj++) {
            float lo = __uint_as_float((unsigned int)(acc[r][jj] & 0xffffffffULL));
            float hi = __uint_as_float((unsigned int)(acc[r][jj] >> 32));
            float s  = (lo + hi) * -0.125f;   // -1/sqrt(64)
            int i = ig + 8 * r;
            int j = jg + 4 * jj;
            smem[i * OSTR + j * NH + h] = s;
        }
    __syncthreads();

    // Coalesced store: 32 i-rows x 128 floats = 1024 float4, 4 passes.
#pragma unroll
    for (int pass = 0; pass < 4; pass++) {
        int sidx = pass * 256 + tid;
        int c4   = sidx & 31;              // float4 index within row
        int i    = sidx >> 5;              // 0..31
        float4 v = *reinterpret_cast<const float4*>(&smem[i * OSTR + c4 * 4]);
        *reinterpret_cast<float4*>(
            out + (((b * NCTX + i0 + i) * NCTX + j0) * NH) + c4 * 4) = v;
    }
}

extern "C" void kernel_launch(void* const* d_in, const int* in_sizes, int n_in,
                              void* d_out, int out_size) {
    const float* q = (const float*)d_in[0];
    const float* k = (const float*)d_in[1];
    float* out = (float*)d_out;
    int bs = in_sizes[0] / (NCTX * NH * WID);   // = 2
    dim3 grid(NCTX / TJ, NCTX / TI, bs);
    l1attn_kernel<<<grid, 256>>>(q, k, out);
}